// round 12
// baseline (speedup 1.0000x reference)
#include <cuda_runtime.h>
#include <cuda_fp16.h>
#include <math.h>

#define Bq 64
#define Tq 512
#define Iq 512
#define Hq 1024
#define Oq 512
#define Gq 3072

// -------- scratch (device globals) --------
__device__ float  g_xp[(size_t)Tq * Bq * Gq];      // [t][b][3H] fp32
__device__ __half g_hs16[(size_t)Bq * Tq * Hq];    // [b][t][H]
__device__ uint2  g_hr[2][64 * 64 * 4];            // h ring, fragment layout [k16][b][q]
__device__ __half g_x16[(size_t)Tq * Bq * Iq];     // inputs, [t*64+b][I] fp16
__device__ __half g_wih16[(size_t)Gq * Iq];
__device__ __half g_wout16[(size_t)Oq * Hq];
__device__ unsigned g_flag2[64];                   // arrival counters: +16 per step
__device__ unsigned g_gen2 = 0;

// -------- helpers --------
__device__ __forceinline__ unsigned pk2(float a, float b) {
    __half2 h = __floats2half2_rn(a, b);
    return *reinterpret_cast<unsigned*>(&h);
}
__device__ __forceinline__ void mma_f16(
    float& d0, float& d1, float& d2, float& d3,
    unsigned a0, unsigned a1, unsigned a2, unsigned a3,
    unsigned b0, unsigned b1)
{
    asm volatile(
        "mma.sync.aligned.m16n8k16.row.col.f32.f16.f16.f32 "
        "{%0,%1,%2,%3},{%4,%5,%6,%7},{%8,%9},{%0,%1,%2,%3};"
        : "+f"(d0), "+f"(d1), "+f"(d2), "+f"(d3)
        : "r"(a0), "r"(a1), "r"(a2), "r"(a3), "r"(b0), "r"(b1));
}
__device__ __forceinline__ void red_add_release_gpu(unsigned* p, unsigned v) {
    asm volatile("red.add.release.gpu.global.u32 [%0], %1;" :: "l"(p), "r"(v) : "memory");
}
__device__ __forceinline__ unsigned ld_acquire_gpu(const unsigned* p) {
    unsigned v;
    asm volatile("ld.acquire.gpu.global.u32 %0, [%1];" : "=r"(v) : "l"(p) : "memory");
    return v;
}
__device__ __forceinline__ uint2 ldcg_u2(const uint2* p) {
    uint2 v;
    asm volatile("ld.global.cg.v2.u32 {%0,%1}, [%2];" : "=r"(v.x), "=r"(v.y) : "l"(p));
    return v;
}

// MUFU-free sigmoid (FFMA/ALU only)
__device__ __forceinline__ float sigm_fast(float x) {
    const float L2E = 1.4426950408889634f;
    const float MAGIC = 12582912.0f;
    float xc = fminf(fmaxf(x, -87.0f), 87.0f);
    float t = fmaf(xc, -L2E, MAGIC);
    float nf = t - MAGIC;
    float f = fmaf(xc, -L2E, -nf);
    float p = 1.3333558146e-3f;
    p = fmaf(p, f, 9.6181291076e-3f);
    p = fmaf(p, f, 5.5504108665e-2f);
    p = fmaf(p, f, 2.4022650696e-1f);
    p = fmaf(p, f, 6.9314718056e-1f);
    p = fmaf(p, f, 1.0f);
    int ni = __float_as_int(t) - 0x4B400000;
    float sc = __int_as_float((ni << 23) + 0x3F800000);
    float E = p * sc;
    float d = 1.0f + E;
    float r = __int_as_float(0x7EF311C7 - __float_as_int(d));
    r = r * fmaf(-d, r, 2.0f);
    r = r * fmaf(-d, r, 2.0f);
    r = r * fmaf(-d, r, 2.0f);
    return r;
}
__device__ __forceinline__ float tanh_fast(float x) {
    return fmaf(2.0f, sigm_fast(2.0f * x), -1.0f);
}

__global__ void noop_kernel() {}

// ============================================================================
// Merged conversion kernel: x16 [0,8192) | weights [8192,9216) | h0-ring [9216,9232)
// ============================================================================
__global__ __launch_bounds__(256) void cvt_all_kernel(
    const float* __restrict__ inputs, const float* __restrict__ w_ih,
    const float* __restrict__ w_out, const float* __restrict__ h0,
    __half* __restrict__ x16, __half* __restrict__ wih16,
    __half* __restrict__ wout16, uint2* __restrict__ ring1)
{
    const int bid = blockIdx.x;
    const int tid = threadIdx.x;
    if (bid < 8192) {
        const int idx = bid * 256 + tid;
        const int m = idx >> 6;
        const int c = idx & 63;
        const float* src = inputs + ((size_t)(m & 63) * Tq + (size_t)(m >> 6)) * Iq + c * 8;
        const float4 f0 = __ldg((const float4*)src);
        const float4 f1 = __ldg((const float4*)(src + 4));
        uint4 o;
        o.x = pk2(f0.x, f0.y); o.y = pk2(f0.z, f0.w);
        o.z = pk2(f1.x, f1.y); o.w = pk2(f1.z, f1.w);
        *(uint4*)(x16 + (size_t)m * Iq + c * 8) = o;
    } else if (bid < 9216) {
        const int idx = (bid - 8192) * 256 + tid;
        const int NIH = (Gq * Iq) / 8;
        const float* src;
        __half* dst;
        int off;
        if (idx < NIH) { src = w_ih; dst = wih16; off = idx * 8; }
        else           { src = w_out; dst = wout16; off = (idx - NIH) * 8; }
        const float4 f0 = __ldg((const float4*)(src + off));
        const float4 f1 = __ldg((const float4*)(src + off + 4));
        uint4 o;
        o.x = pk2(f0.x, f0.y); o.y = pk2(f0.z, f0.w);
        o.z = pk2(f1.x, f1.y); o.w = pk2(f1.z, f1.w);
        *(uint4*)(dst + off) = o;
    } else {
        const int idx = (bid - 9216) * 256 + tid;   // [0,4096)
        const int b = idx & 63;
        const int k16 = idx >> 6;
        const float* p = h0 + (size_t)b * Hq + k16 * 16;
        const float4 f0 = __ldg((const float4*)p);
        const float4 f1 = __ldg((const float4*)(p + 4));
        const float4 f2 = __ldg((const float4*)(p + 8));
        const float4 f3 = __ldg((const float4*)(p + 12));
        uint2* d = ring1 + ((size_t)k16 * 64 + b) * 4;
        d[0] = make_uint2(pk2(f0.x, f0.y), pk2(f2.x, f2.y));
        d[1] = make_uint2(pk2(f0.z, f0.w), pk2(f2.z, f2.w));
        d[2] = make_uint2(pk2(f1.x, f1.y), pk2(f3.x, f3.y));
        d[3] = make_uint2(pk2(f1.z, f1.w), pk2(f3.z, f3.w));
    }
}

// ============================================================================
// Pure-fp16 MMA GEMM (K1/K3), block tile 128x64, k-tile 64, 256 threads.
// ============================================================================
#define APIT 513
#define BPIT 257

__global__ __launch_bounds__(256) void mma_gemm16(
    const __half* __restrict__ A16, const __half* __restrict__ B16,
    const float* __restrict__ bias, float* __restrict__ C,
    int N, int K)
{
    __shared__ __align__(16) uint2 As2[4 * APIT];
    __shared__ __align__(16) uint2 Bs2[4 * BPIT];

    const int tid = threadIdx.x;
    const int m0 = blockIdx.y * 128, n0 = blockIdx.x * 64;
    const int lane = tid & 31, warp = tid >> 5;
    const int g = lane >> 2, q = lane & 3;
    const int wm = warp >> 1, wn = warp & 1;

    const int ap = tid & 3;
    const int ar = tid >> 2;
    size_t arow[2];
#pragma unroll
    for (int i = 0; i < 2; i++) arow[i] = (size_t)(m0 + ar + i * 64) * (size_t)K;
    const size_t brow = (size_t)(n0 + ar) * (size_t)K;

    float acc[2][4][4];
#pragma unroll
    for (int mt = 0; mt < 2; mt++)
#pragma unroll
        for (int nt = 0; nt < 4; nt++)
#pragma unroll
            for (int e = 0; e < 4; e++) acc[mt][nt][e] = 0.0f;

    uint4 ha[2][2], hb[2];
#pragma unroll
    for (int i = 0; i < 2; i++) {
        ha[i][0] = __ldg((const uint4*)(A16 + arow[i] + ap * 16));
        ha[i][1] = __ldg((const uint4*)(A16 + arow[i] + ap * 16 + 8));
    }
    hb[0] = __ldg((const uint4*)(B16 + brow + ap * 16));
    hb[1] = __ldg((const uint4*)(B16 + brow + ap * 16 + 8));

    for (int k0 = 0; k0 < K; k0 += 64) {
#pragma unroll
        for (int i = 0; i < 2; i++) {
            uint2* d = &As2[ap * APIT + (ar + i * 64) * 4];
            d[0] = make_uint2(ha[i][0].x, ha[i][1].x);
            d[1] = make_uint2(ha[i][0].y, ha[i][1].y);
            d[2] = make_uint2(ha[i][0].z, ha[i][1].z);
            d[3] = make_uint2(ha[i][0].w, ha[i][1].w);
        }
        {
            uint2* d = &Bs2[ap * BPIT + ar * 4];
            d[0] = make_uint2(hb[0].x, hb[1].x);
            d[1] = make_uint2(hb[0].y, hb[1].y);
            d[2] = make_uint2(hb[0].z, hb[1].z);
            d[3] = make_uint2(hb[0].w, hb[1].w);
        }
        __syncthreads();

        if (k0 + 64 < K) {
#pragma unroll
            for (int i = 0; i < 2; i++) {
                ha[i][0] = __ldg((const uint4*)(A16 + arow[i] + k0 + 64 + ap * 16));
                ha[i][1] = __ldg((const uint4*)(A16 + arow[i] + k0 + 64 + ap * 16 + 8));
            }
            hb[0] = __ldg((const uint4*)(B16 + brow + k0 + 64 + ap * 16));
            hb[1] = __ldg((const uint4*)(B16 + brow + k0 + 64 + ap * 16 + 8));
        }

#pragma unroll
        for (int p = 0; p < 4; p++) {
            uint2 aLo[2], aHi[2];
#pragma unroll
            for (int mt = 0; mt < 2; mt++) {
                const int r = wm * 32 + mt * 16 + g;
                aLo[mt] = As2[p * APIT + r * 4 + q];
                aHi[mt] = As2[p * APIT + (r + 8) * 4 + q];
            }
#pragma unroll
            for (int nt = 0; nt < 4; nt++) {
                const uint2 bb = Bs2[p * BPIT + (wn * 32 + nt * 8 + g) * 4 + q];
#pragma unroll
                for (int mt = 0; mt < 2; mt++)
                    mma_f16(acc[mt][nt][0], acc[mt][nt][1], acc[mt][nt][2], acc[mt][nt][3],
                            aLo[mt].x, aHi[mt].x, aLo[mt].y, aHi[mt].y, bb.x, bb.y);
            }
        }
        __syncthreads();
    }

#pragma unroll
    for (int mt = 0; mt < 2; mt++) {
        const int mrow = m0 + wm * 32 + mt * 16 + g;
#pragma unroll
        for (int nt = 0; nt < 4; nt++) {
            const int col = n0 + wn * 32 + nt * 8 + 2 * q;
            const float2 bb = *(const float2*)&bias[col];
            float2 o0, o1;
            o0.x = acc[mt][nt][0] + bb.x; o0.y = acc[mt][nt][1] + bb.y;
            o1.x = acc[mt][nt][2] + bb.x; o1.y = acc[mt][nt][3] + bb.y;
            *(float2*)&C[(size_t)mrow * N + col] = o0;
            *(float2*)&C[(size_t)(mrow + 8) * N + col] = o1;
        }
    }
}

// ============================================================================
// Persistent GRU recurrence: 512 threads / 16 warps = 4 m-groups x 4 k-quarters.
// Per warp: m16 x n48 x k256 (A direct from L2 ring). Same total traffic as R11,
// 2x warps per SMSP for latency hiding. Double-buffered reduce scratch, one
// block sync per step, per-warp arrival-counter release (+16/step).
// ============================================================================
#define NB2 64
#define NT2 512
#define WPLANE 192
#define WS_U2 (64 * WPLANE)
#define REDP 52
#define RED_HALF (16 * 16 * REDP)                     // floats per t-parity buffer
#define K2_SMEM (WS_U2 * 8 + 2 * RED_HALF * 4)        // 98304 + 106496 = 204800 B

__global__ __launch_bounds__(NT2, 1) void gru_rec_mma(
    const float* __restrict__ xp, const float* __restrict__ h0,
    const float* __restrict__ w_hh, const float* __restrict__ b_hh,
    __half* __restrict__ hs16)
{
    extern __shared__ uint2 sm2[];
    uint2* Ws2 = sm2;                       // resident weights
    float* Redf0 = (float*)(sm2 + WS_U2);   // k-reduce exchange (x2, by t&1)

    const int tid = threadIdx.x;
    const int lane = tid & 31, warp = tid >> 5;
    const int g = lane >> 2, q = lane & 3;
    const int wk = warp >> 2;               // k-quarter 0..3
    const int wm = warp & 3;                // m-group 0..3
    const int k16blk = blockIdx.x;
    const int hc0 = k16blk * 16;

    // resident weights (fp16 pairs)
    for (int idx = tid; idx < WS_U2; idx += NT2) {
        const int k16 = idx / WPLANE;
        const int r = idx - k16 * WPLANE;
        const int n = r >> 2, qq = r & 3;
        const float* src = w_hh + ((size_t)(n >> 4) * Hq + hc0 + (n & 15)) * Hq + k16 * 16;
        Ws2[idx] = make_uint2(pk2(src[2 * qq], src[2 * qq + 1]),
                              pk2(src[2 * qq + 8], src[2 * qq + 9]));
    }

    // gate ownership: thread -> b = tid>>3, col pair gcp = tid&7 (cols hc0+2*gcp, +1)
    const int gb = tid >> 3;
    const int gcp = tid & 7;
    const int hc = hc0 + gcp * 2;
    const float2 bhr = *(const float2*)&b_hh[hc];
    const float2 bhz = *(const float2*)&b_hh[Hq + hc];
    const float2 bhn = *(const float2*)&b_hh[2 * Hq + hc];
    float2 h_prev = *(const float2*)&h0[(size_t)gb * Hq + hc];

    // ring u32 index for this thread's col pair
    const int ru32 = (gcp & 3) * 2 + (gcp >> 2);

    const unsigned G0 = g_gen2;
    __syncthreads();

    for (int t = 0; t < Tq; t++) {
        const uint2* rbuf = g_hr[(t - 1) & 1];
        uint2* rnew = g_hr[t & 1];
        float* Redf = Redf0 + (t & 1) * RED_HALF;

        // xp prefetch (issued before poll; consumed at gates)
        const float* xpb = xp + ((size_t)t * 64 + gb) * Gq + hc;
        const float2 pxr = __ldg((const float2*)xpb);
        const float2 pxz = __ldg((const float2*)(xpb + Hq));
        const float2 pxn = __ldg((const float2*)(xpb + 2 * Hq));

        // ---- warp-local acquire poll: this warp's 16 source planes ----
        if (t > 0) {
            const unsigned need = 16u * (G0 + (unsigned)t);
            if (lane < 16) {
                while (ld_acquire_gpu(&g_flag2[wk * 16 + lane]) < need) { }
            }
            __syncwarp();
        }

        // ---- GEMM: warp = m16 x n48 x k256, A direct from L2 ring ----
        float acc[6][4];
#pragma unroll
        for (int nt = 0; nt < 6; nt++)
#pragma unroll
            for (int e = 0; e < 4; e++) acc[nt][e] = 0.0f;

        const int kb = wk * 16;
        const int r0 = wm * 16 + g;
#pragma unroll 8
        for (int kk = 0; kk < 16; kk++) {
            const uint2* ra = rbuf + (size_t)(kb + kk) * 256;
            const uint2 aLo = ldcg_u2(ra + r0 * 4 + q);
            const uint2 aHi = ldcg_u2(ra + (r0 + 8) * 4 + q);
            const uint2* wp = Ws2 + (size_t)(kb + kk) * WPLANE;
#pragma unroll
            for (int nt = 0; nt < 6; nt++) {
                const uint2 bb = wp[(nt * 8 + g) * 4 + q];
                mma_f16(acc[nt][0], acc[nt][1], acc[nt][2], acc[nt][3],
                        aLo.x, aHi.x, aLo.y, aHi.y, bb.x, bb.y);
            }
        }

        // ---- publish partials (region = wk*4+wm, 16 rows x 48 cols) ----
        {
            float* red = Redf + (wk * 4 + wm) * (16 * REDP);
#pragma unroll
            for (int nt = 0; nt < 6; nt++) {
                *(float2*)&red[g * REDP + nt * 8 + 2 * q] =
                    make_float2(acc[nt][0], acc[nt][1]);
                *(float2*)&red[(g + 8) * REDP + nt * 8 + 2 * q] =
                    make_float2(acc[nt][2], acc[nt][3]);
            }
        }
        __syncthreads();   // the ONLY block sync per step

        // ---- per-thread reduce + gates (2 outputs) ----
        {
            const int wmb = gb >> 4;
            const int row = gb & 15;
            float sr0 = 0, sr1 = 0, sz0 = 0, sz1 = 0, sn0 = 0, sn1 = 0;
#pragma unroll
            for (int k4 = 0; k4 < 4; k4++) {
                const float* red = Redf + (k4 * 4 + wmb) * (16 * REDP) + row * REDP;
                const float2 vr = *(const float2*)&red[0 * 16 + gcp * 2];
                const float2 vz = *(const float2*)&red[1 * 16 + gcp * 2];
                const float2 vn = *(const float2*)&red[2 * 16 + gcp * 2];
                sr0 += vr.x; sr1 += vr.y;
                sz0 += vz.x; sz1 += vz.y;
                sn0 += vn.x; sn1 += vn.y;
            }
            float hv0, hv1;
            {
                const float r = sigm_fast(pxr.x + sr0 + bhr.x);
                const float z = sigm_fast(pxz.x + sz0 + bhz.x);
                const float nn = tanh_fast(pxn.x + r * (sn0 + bhn.x));
                hv0 = (1.0f - z) * nn + z * h_prev.x;
            }
            {
                const float r = sigm_fast(pxr.y + sr1 + bhr.y);
                const float z = sigm_fast(pxz.y + sz1 + bhz.y);
                const float nn = tanh_fast(pxn.y + r * (sn1 + bhn.y));
                hv1 = (1.0f - z) * nn + z * h_prev.y;
            }
            h_prev = make_float2(hv0, hv1);
            const unsigned p0 = pk2(hv0, hv1);
            unsigned* rb32 = (unsigned*)(rnew + ((size_t)k16blk * 64 + gb) * 4);
            rb32[ru32] = p0;
            *(unsigned*)(hs16 + ((size_t)gb * Tq + t) * Hq + hc) = p0;
        }

        // ---- per-warp arrival release (warp w wrote ring rows [4w, 4w+4)) ----
        __syncwarp();
        if (lane == 0) red_add_release_gpu(&g_flag2[blockIdx.x], 1u);
    }

    if (blockIdx.x == 0 && tid == 0) {
        __threadfence();
        g_gen2 = G0 + (unsigned)Tq;
    }
}

__global__ void copy_hlast_kernel(const __half* __restrict__ hs16, float* __restrict__ out)
{
    const int idx = blockIdx.x * 256 + threadIdx.x;
    if (idx < Bq * Hq) {
        const int b = idx >> 10;
        const int h = idx & 1023;
        out[idx] = __half2float(hs16[((size_t)b * Tq + (Tq - 1)) * Hq + h]);
    }
}

// ============================================================================
extern "C" void kernel_launch(void* const* d_in, const int* in_sizes, int n_in,
                              void* d_out, int out_size)
{
    const float* inputs = (const float*)d_in[0];
    const float* h0     = (const float*)d_in[1];
    const float* w_ih   = (const float*)d_in[2];
    const float* w_hh   = (const float*)d_in[3];
    const float* b_ih   = (const float*)d_in[4];
    const float* b_hh   = (const float*)d_in[5];
    const float* w_out  = (const float*)d_in[6];
    const float* b_out  = (const float*)d_in[7];
    float* out = (float*)d_out;

    float* xp;
    __half *hs16, *x16, *wih16, *wout16;
    uint2* hr;
    cudaGetSymbolAddress((void**)&xp, g_xp);
    cudaGetSymbolAddress((void**)&hs16, g_hs16);
    cudaGetSymbolAddress((void**)&x16, g_x16);
    cudaGetSymbolAddress((void**)&wih16, g_wih16);
    cudaGetSymbolAddress((void**)&wout16, g_wout16);
    cudaGetSymbolAddress((void**)&hr, g_hr);

    // keep gru_rec_mma at overall launch #4 (where the profiler lands)
    noop_kernel<<<1, 32>>>();

    // all conversions in one kernel (x16 | weights | h0 -> ring buf 1)
    cvt_all_kernel<<<9232, 256>>>(inputs, w_ih, w_out, h0,
                                  x16, wih16, wout16, hr + 64 * 64 * 4);

    // K1: x_proj
    {
        dim3 grid(Gq / 64, (Tq * Bq) / 128);
        mma_gemm16<<<grid, 256>>>(x16, wih16, b_ih, xp, Gq, Iq);
    }

    // K2: persistent GRU recurrence
    cudaFuncSetAttribute(gru_rec_mma, cudaFuncAttributeMaxDynamicSharedMemorySize, K2_SMEM);
    gru_rec_mma<<<NB2, NT2, K2_SMEM>>>(xp, h0, w_hh, b_hh, hs16);

    // K3: out = hs16 @ wout16^T + b_out
    {
        dim3 grid(Oq / 64, (Bq * Tq) / 128);
        mma_gemm16<<<grid, 256>>>(hs16, wout16, b_out, out, Oq, Hq);
    }

    // K4: h_last tail
    copy_hlast_kernel<<<(Bq * Hq) / 256, 256>>>(hs16, out + (size_t)Bq * Tq * Oq);
}

// round 13
// speedup vs baseline: 1.4359x; 1.4359x over previous
#include <cuda_runtime.h>
#include <cuda_fp16.h>
#include <math.h>

#define Bq 64
#define Tq 512
#define Iq 512
#define Hq 1024
#define Oq 512
#define Gq 3072

// -------- scratch (device globals) --------
__device__ float  g_xp[(size_t)Tq * Bq * Gq];      // [t][b][3H] fp32
__device__ __half g_hs16[(size_t)Bq * Tq * Hq];    // [b][t][H]
__device__ uint2  g_hr[2][64 * 64 * 4];            // h ring, fragment layout [k16][b][q]
__device__ __half g_x16[(size_t)Tq * Bq * Iq];     // inputs, [t*64+b][I] fp16
__device__ __half g_wih16[(size_t)Gq * Iq];
__device__ __half g_wout16[(size_t)Oq * Hq];
__device__ unsigned g_flag2[128];                  // arrival counters: +8 per step per block
__device__ unsigned g_gen2 = 0;

// -------- helpers --------
__device__ __forceinline__ unsigned pk2(float a, float b) {
    __half2 h = __floats2half2_rn(a, b);
    return *reinterpret_cast<unsigned*>(&h);
}
__device__ __forceinline__ void mma_f16(
    float& d0, float& d1, float& d2, float& d3,
    unsigned a0, unsigned a1, unsigned a2, unsigned a3,
    unsigned b0, unsigned b1)
{
    asm volatile(
        "mma.sync.aligned.m16n8k16.row.col.f32.f16.f16.f32 "
        "{%0,%1,%2,%3},{%4,%5,%6,%7},{%8,%9},{%0,%1,%2,%3};"
        : "+f"(d0), "+f"(d1), "+f"(d2), "+f"(d3)
        : "r"(a0), "r"(a1), "r"(a2), "r"(a3), "r"(b0), "r"(b1));
}
__device__ __forceinline__ void red_add_release_gpu(unsigned* p, unsigned v) {
    asm volatile("red.add.release.gpu.global.u32 [%0], %1;" :: "l"(p), "r"(v) : "memory");
}
__device__ __forceinline__ unsigned ld_acquire_gpu(const unsigned* p) {
    unsigned v;
    asm volatile("ld.acquire.gpu.global.u32 %0, [%1];" : "=r"(v) : "l"(p) : "memory");
    return v;
}
__device__ __forceinline__ uint2 ldcg_u2(const uint2* p) {
    uint2 v;
    asm volatile("ld.global.cg.v2.u32 {%0,%1}, [%2];" : "=r"(v.x), "=r"(v.y) : "l"(p));
    return v;
}

// MUFU-free sigmoid (FFMA/ALU only)
__device__ __forceinline__ float sigm_fast(float x) {
    const float L2E = 1.4426950408889634f;
    const float MAGIC = 12582912.0f;
    float xc = fminf(fmaxf(x, -87.0f), 87.0f);
    float t = fmaf(xc, -L2E, MAGIC);
    float nf = t - MAGIC;
    float f = fmaf(xc, -L2E, -nf);
    float p = 1.3333558146e-3f;
    p = fmaf(p, f, 9.6181291076e-3f);
    p = fmaf(p, f, 5.5504108665e-2f);
    p = fmaf(p, f, 2.4022650696e-1f);
    p = fmaf(p, f, 6.9314718056e-1f);
    p = fmaf(p, f, 1.0f);
    int ni = __float_as_int(t) - 0x4B400000;
    float sc = __int_as_float((ni << 23) + 0x3F800000);
    float E = p * sc;
    float d = 1.0f + E;
    float r = __int_as_float(0x7EF311C7 - __float_as_int(d));
    r = r * fmaf(-d, r, 2.0f);
    r = r * fmaf(-d, r, 2.0f);
    r = r * fmaf(-d, r, 2.0f);
    return r;
}
__device__ __forceinline__ float tanh_fast(float x) {
    return fmaf(2.0f, sigm_fast(2.0f * x), -1.0f);
}

__global__ void noop_kernel() {}

// ============================================================================
// Merged conversion kernel: x16 [0,8192) | weights [8192,9216) | h0-ring [9216,9232)
// ============================================================================
__global__ __launch_bounds__(256) void cvt_all_kernel(
    const float* __restrict__ inputs, const float* __restrict__ w_ih,
    const float* __restrict__ w_out, const float* __restrict__ h0,
    __half* __restrict__ x16, __half* __restrict__ wih16,
    __half* __restrict__ wout16, uint2* __restrict__ ring1)
{
    const int bid = blockIdx.x;
    const int tid = threadIdx.x;
    if (bid < 8192) {
        const int idx = bid * 256 + tid;
        const int m = idx >> 6;
        const int c = idx & 63;
        const float* src = inputs + ((size_t)(m & 63) * Tq + (size_t)(m >> 6)) * Iq + c * 8;
        const float4 f0 = __ldg((const float4*)src);
        const float4 f1 = __ldg((const float4*)(src + 4));
        uint4 o;
        o.x = pk2(f0.x, f0.y); o.y = pk2(f0.z, f0.w);
        o.z = pk2(f1.x, f1.y); o.w = pk2(f1.z, f1.w);
        *(uint4*)(x16 + (size_t)m * Iq + c * 8) = o;
    } else if (bid < 9216) {
        const int idx = (bid - 8192) * 256 + tid;
        const int NIH = (Gq * Iq) / 8;
        const float* src;
        __half* dst;
        int off;
        if (idx < NIH) { src = w_ih; dst = wih16; off = idx * 8; }
        else           { src = w_out; dst = wout16; off = (idx - NIH) * 8; }
        const float4 f0 = __ldg((const float4*)(src + off));
        const float4 f1 = __ldg((const float4*)(src + off + 4));
        uint4 o;
        o.x = pk2(f0.x, f0.y); o.y = pk2(f0.z, f0.w);
        o.z = pk2(f1.x, f1.y); o.w = pk2(f1.z, f1.w);
        *(uint4*)(dst + off) = o;
    } else {
        const int idx = (bid - 9216) * 256 + tid;   // [0,4096)
        const int b = idx & 63;
        const int k16 = idx >> 6;
        const float* p = h0 + (size_t)b * Hq + k16 * 16;
        const float4 f0 = __ldg((const float4*)p);
        const float4 f1 = __ldg((const float4*)(p + 4));
        const float4 f2 = __ldg((const float4*)(p + 8));
        const float4 f3 = __ldg((const float4*)(p + 12));
        uint2* d = ring1 + ((size_t)k16 * 64 + b) * 4;
        d[0] = make_uint2(pk2(f0.x, f0.y), pk2(f2.x, f2.y));
        d[1] = make_uint2(pk2(f0.z, f0.w), pk2(f2.z, f2.w));
        d[2] = make_uint2(pk2(f1.x, f1.y), pk2(f3.x, f3.y));
        d[3] = make_uint2(pk2(f1.z, f1.w), pk2(f3.z, f3.w));
    }
}

// ============================================================================
// Pure-fp16 MMA GEMM (K1/K3), block tile 128x64, k-tile 64, 256 threads.
// ============================================================================
#define APIT 513
#define BPIT 257

__global__ __launch_bounds__(256) void mma_gemm16(
    const __half* __restrict__ A16, const __half* __restrict__ B16,
    const float* __restrict__ bias, float* __restrict__ C,
    int N, int K)
{
    __shared__ __align__(16) uint2 As2[4 * APIT];
    __shared__ __align__(16) uint2 Bs2[4 * BPIT];

    const int tid = threadIdx.x;
    const int m0 = blockIdx.y * 128, n0 = blockIdx.x * 64;
    const int lane = tid & 31, warp = tid >> 5;
    const int g = lane >> 2, q = lane & 3;
    const int wm = warp >> 1, wn = warp & 1;

    const int ap = tid & 3;
    const int ar = tid >> 2;
    size_t arow[2];
#pragma unroll
    for (int i = 0; i < 2; i++) arow[i] = (size_t)(m0 + ar + i * 64) * (size_t)K;
    const size_t brow = (size_t)(n0 + ar) * (size_t)K;

    float acc[2][4][4];
#pragma unroll
    for (int mt = 0; mt < 2; mt++)
#pragma unroll
        for (int nt = 0; nt < 4; nt++)
#pragma unroll
            for (int e = 0; e < 4; e++) acc[mt][nt][e] = 0.0f;

    uint4 ha[2][2], hb[2];
#pragma unroll
    for (int i = 0; i < 2; i++) {
        ha[i][0] = __ldg((const uint4*)(A16 + arow[i] + ap * 16));
        ha[i][1] = __ldg((const uint4*)(A16 + arow[i] + ap * 16 + 8));
    }
    hb[0] = __ldg((const uint4*)(B16 + brow + ap * 16));
    hb[1] = __ldg((const uint4*)(B16 + brow + ap * 16 + 8));

    for (int k0 = 0; k0 < K; k0 += 64) {
#pragma unroll
        for (int i = 0; i < 2; i++) {
            uint2* d = &As2[ap * APIT + (ar + i * 64) * 4];
            d[0] = make_uint2(ha[i][0].x, ha[i][1].x);
            d[1] = make_uint2(ha[i][0].y, ha[i][1].y);
            d[2] = make_uint2(ha[i][0].z, ha[i][1].z);
            d[3] = make_uint2(ha[i][0].w, ha[i][1].w);
        }
        {
            uint2* d = &Bs2[ap * BPIT + ar * 4];
            d[0] = make_uint2(hb[0].x, hb[1].x);
            d[1] = make_uint2(hb[0].y, hb[1].y);
            d[2] = make_uint2(hb[0].z, hb[1].z);
            d[3] = make_uint2(hb[0].w, hb[1].w);
        }
        __syncthreads();

        if (k0 + 64 < K) {
#pragma unroll
            for (int i = 0; i < 2; i++) {
                ha[i][0] = __ldg((const uint4*)(A16 + arow[i] + k0 + 64 + ap * 16));
                ha[i][1] = __ldg((const uint4*)(A16 + arow[i] + k0 + 64 + ap * 16 + 8));
            }
            hb[0] = __ldg((const uint4*)(B16 + brow + k0 + 64 + ap * 16));
            hb[1] = __ldg((const uint4*)(B16 + brow + k0 + 64 + ap * 16 + 8));
        }

#pragma unroll
        for (int p = 0; p < 4; p++) {
            uint2 aLo[2], aHi[2];
#pragma unroll
            for (int mt = 0; mt < 2; mt++) {
                const int r = wm * 32 + mt * 16 + g;
                aLo[mt] = As2[p * APIT + r * 4 + q];
                aHi[mt] = As2[p * APIT + (r + 8) * 4 + q];
            }
#pragma unroll
            for (int nt = 0; nt < 4; nt++) {
                const uint2 bb = Bs2[p * BPIT + (wn * 32 + nt * 8 + g) * 4 + q];
#pragma unroll
                for (int mt = 0; mt < 2; mt++)
                    mma_f16(acc[mt][nt][0], acc[mt][nt][1], acc[mt][nt][2], acc[mt][nt][3],
                            aLo[mt].x, aHi[mt].x, aLo[mt].y, aHi[mt].y, bb.x, bb.y);
            }
        }
        __syncthreads();
    }

#pragma unroll
    for (int mt = 0; mt < 2; mt++) {
        const int mrow = m0 + wm * 32 + mt * 16 + g;
#pragma unroll
        for (int nt = 0; nt < 4; nt++) {
            const int col = n0 + wn * 32 + nt * 8 + 2 * q;
            const float2 bb = *(const float2*)&bias[col];
            float2 o0, o1;
            o0.x = acc[mt][nt][0] + bb.x; o0.y = acc[mt][nt][1] + bb.y;
            o1.x = acc[mt][nt][2] + bb.x; o1.y = acc[mt][nt][3] + bb.y;
            *(float2*)&C[(size_t)mrow * N + col] = o0;
            *(float2*)&C[(size_t)(mrow + 8) * N + col] = o1;
        }
    }
}

// ============================================================================
// Persistent GRU recurrence: 128 blocks = 64 col-groups x 2 batch-halves.
// Block: m32 x n48 x k1024, 256 threads / 8 warps = 4 k-quarters x 2 m-groups.
// Half the work per block of R11, same total L2 ring traffic. Weights resident
// (96KB, duplicated per half). Plane p produced by blocks {2p, 2p+1}; warp wk
// polls its 32 source-block flags. One block sync per step; per-warp releases.
// ============================================================================
#define NB2 128
#define WPLANE 192
#define WS_U2 (64 * WPLANE)
#define REDP 52
#define RED_HALF (8 * 16 * REDP)                      // floats per t-parity buffer
#define K2_SMEM (WS_U2 * 8 + 2 * RED_HALF * 4)        // 98304 + 53248 = 151552 B

__global__ __launch_bounds__(256, 1) void gru_rec_mma(
    const float* __restrict__ xp, const float* __restrict__ h0,
    const float* __restrict__ w_hh, const float* __restrict__ b_hh,
    __half* __restrict__ hs16, float* __restrict__ out_tail)
{
    extern __shared__ uint2 sm2[];
    uint2* Ws2 = sm2;                       // resident weights
    float* Redf0 = (float*)(sm2 + WS_U2);   // k-reduce exchange (x2, by t&1)

    const int tid = threadIdx.x;
    const int lane = tid & 31, warp = tid >> 5;
    const int g = lane >> 2, q = lane & 3;
    const int wk = warp >> 1, wm2 = warp & 1;
    const int cg = blockIdx.x >> 1;         // col group == ring plane this block writes
    const int bh = blockIdx.x & 1;          // batch half
    const int hc0 = cg * 16;
    const int bb0 = bh * 32;

    // resident weights (fp16 pairs), keyed by col group
    for (int idx = tid; idx < WS_U2; idx += 256) {
        const int k16 = idx / WPLANE;
        const int r = idx - k16 * WPLANE;
        const int n = r >> 2, qq = r & 3;
        const float* src = w_hh + ((size_t)(n >> 4) * Hq + hc0 + (n & 15)) * Hq + k16 * 16;
        Ws2[idx] = make_uint2(pk2(src[2 * qq], src[2 * qq + 1]),
                              pk2(src[2 * qq + 8], src[2 * qq + 9]));
    }

    // gate ownership: thread -> row pr = tid>>3 (batch bb0+pr), col pair gcp = tid&7
    const int pr = tid >> 3;
    const int gb = bb0 + pr;
    const int gcp = tid & 7;
    const int hc = hc0 + gcp * 2;
    const float2 bhr = *(const float2*)&b_hh[hc];
    const float2 bhz = *(const float2*)&b_hh[Hq + hc];
    const float2 bhn = *(const float2*)&b_hh[2 * Hq + hc];
    float2 h_prev = *(const float2*)&h0[(size_t)gb * Hq + hc];

    // ring u32 index for this thread's col pair
    const int ru32 = (gcp & 3) * 2 + (gcp >> 2);

    const unsigned G0 = g_gen2;
    __syncthreads();

    for (int t = 0; t < Tq; t++) {
        const uint2* rbuf = g_hr[(t - 1) & 1];
        uint2* rnew = g_hr[t & 1];
        float* Redf = Redf0 + (t & 1) * RED_HALF;

        // xp prefetch (issued before poll; consumed at gates)
        const float* xpb = xp + ((size_t)t * 64 + gb) * Gq + hc;
        const float2 pxr = __ldg((const float2*)xpb);
        const float2 pxz = __ldg((const float2*)(xpb + Hq));
        const float2 pxn = __ldg((const float2*)(xpb + 2 * Hq));

        // ---- warp-local acquire poll: 32 source blocks of this warp's planes ----
        if (t > 0) {
            const unsigned need = 8u * (G0 + (unsigned)t);
            while (ld_acquire_gpu(&g_flag2[wk * 32 + lane]) < need) { }
            __syncwarp();
        }

        // ---- GEMM: warp = m16 x n48 x k256, A direct from L2 ring ----
        float acc[6][4];
#pragma unroll
        for (int nt = 0; nt < 6; nt++)
#pragma unroll
            for (int e = 0; e < 4; e++) acc[nt][e] = 0.0f;

        const int kb = wk * 16;
        const int r0 = bb0 + wm2 * 16 + g;
#pragma unroll
        for (int kk = 0; kk < 16; kk++) {
            const uint2* ra = rbuf + (size_t)(kb + kk) * 256;
            const uint2 aLo = ldcg_u2(ra + r0 * 4 + q);
            const uint2 aHi = ldcg_u2(ra + (r0 + 8) * 4 + q);
            const uint2* wp = Ws2 + (size_t)(kb + kk) * WPLANE;
#pragma unroll
            for (int nt = 0; nt < 6; nt++) {
                const uint2 bb = wp[(nt * 8 + g) * 4 + q];
                mma_f16(acc[nt][0], acc[nt][1], acc[nt][2], acc[nt][3],
                        aLo.x, aHi.x, aLo.y, aHi.y, bb.x, bb.y);
            }
        }

        // ---- publish partials (region = wk*2 + wm2, 16 rows x 48 cols) ----
        {
            float* red = Redf + (wk * 2 + wm2) * (16 * REDP);
#pragma unroll
            for (int nt = 0; nt < 6; nt++) {
                *(float2*)&red[g * REDP + nt * 8 + 2 * q] =
                    make_float2(acc[nt][0], acc[nt][1]);
                *(float2*)&red[(g + 8) * REDP + nt * 8 + 2 * q] =
                    make_float2(acc[nt][2], acc[nt][3]);
            }
        }
        __syncthreads();   // the ONLY block sync per step

        // ---- per-thread reduce + gates (2 outputs) ----
        {
            const int wmb = pr >> 4;
            const int row = pr & 15;
            float sr0 = 0, sr1 = 0, sz0 = 0, sz1 = 0, sn0 = 0, sn1 = 0;
#pragma unroll
            for (int k4 = 0; k4 < 4; k4++) {
                const float* red = Redf + (k4 * 2 + wmb) * (16 * REDP) + row * REDP;
                const float2 vr = *(const float2*)&red[0 * 16 + gcp * 2];
                const float2 vz = *(const float2*)&red[1 * 16 + gcp * 2];
                const float2 vn = *(const float2*)&red[2 * 16 + gcp * 2];
                sr0 += vr.x; sr1 += vr.y;
                sz0 += vz.x; sz1 += vz.y;
                sn0 += vn.x; sn1 += vn.y;
            }
            float hv0, hv1;
            {
                const float r = sigm_fast(pxr.x + sr0 + bhr.x);
                const float z = sigm_fast(pxz.x + sz0 + bhz.x);
                const float nn = tanh_fast(pxn.x + r * (sn0 + bhn.x));
                hv0 = (1.0f - z) * nn + z * h_prev.x;
            }
            {
                const float r = sigm_fast(pxr.y + sr1 + bhr.y);
                const float z = sigm_fast(pxz.y + sz1 + bhz.y);
                const float nn = tanh_fast(pxn.y + r * (sn1 + bhn.y));
                hv1 = (1.0f - z) * nn + z * h_prev.y;
            }
            h_prev = make_float2(hv0, hv1);
            const unsigned p0 = pk2(hv0, hv1);

            // ring write (critical path), then release, then history (off path)
            unsigned* rb32 = (unsigned*)(rnew + ((size_t)cg * 64 + gb) * 4);
            rb32[ru32] = p0;
            __syncwarp();
            if (lane == 0) red_add_release_gpu(&g_flag2[blockIdx.x], 1u);

            *(unsigned*)(hs16 + ((size_t)gb * Tq + t) * Hq + hc) = p0;
            if (t == Tq - 1)
                *(float2*)&out_tail[(size_t)gb * Hq + hc] = make_float2(hv0, hv1);
        }
    }

    if (blockIdx.x == 0 && tid == 0) {
        __threadfence();
        g_gen2 = G0 + (unsigned)Tq;
    }
}

// ============================================================================
extern "C" void kernel_launch(void* const* d_in, const int* in_sizes, int n_in,
                              void* d_out, int out_size)
{
    const float* inputs = (const float*)d_in[0];
    const float* h0     = (const float*)d_in[1];
    const float* w_ih   = (const float*)d_in[2];
    const float* w_hh   = (const float*)d_in[3];
    const float* b_ih   = (const float*)d_in[4];
    const float* b_hh   = (const float*)d_in[5];
    const float* w_out  = (const float*)d_in[6];
    const float* b_out  = (const float*)d_in[7];
    float* out = (float*)d_out;

    float* xp;
    __half *hs16, *x16, *wih16, *wout16;
    uint2* hr;
    cudaGetSymbolAddress((void**)&xp, g_xp);
    cudaGetSymbolAddress((void**)&hs16, g_hs16);
    cudaGetSymbolAddress((void**)&x16, g_x16);
    cudaGetSymbolAddress((void**)&wih16, g_wih16);
    cudaGetSymbolAddress((void**)&wout16, g_wout16);
    cudaGetSymbolAddress((void**)&hr, g_hr);

    // keep gru_rec_mma at overall launch #4 (where the profiler lands)
    noop_kernel<<<1, 32>>>();

    // all conversions in one kernel (x16 | weights | h0 -> ring buf 1)
    cvt_all_kernel<<<9232, 256>>>(inputs, w_ih, w_out, h0,
                                  x16, wih16, wout16, hr + 64 * 64 * 4);

    // K1: x_proj
    {
        dim3 grid(Gq / 64, (Tq * Bq) / 128);
        mma_gemm16<<<grid, 256>>>(x16, wih16, b_ih, xp, Gq, Iq);
    }

    // K2: persistent GRU recurrence (writes hs16 and the h_last tail directly)
    cudaFuncSetAttribute(gru_rec_mma, cudaFuncAttributeMaxDynamicSharedMemorySize, K2_SMEM);
    gru_rec_mma<<<NB2, 256, K2_SMEM>>>(xp, h0, w_hh, b_hh, hs16,
                                       out + (size_t)Bq * Tq * Oq);

    // K3: out = hs16 @ wout16^T + b_out
    {
        dim3 grid(Oq / 64, (Bq * Tq) / 128);
        mma_gemm16<<<grid, 256>>>(hs16, wout16, b_out, out, Oq, Hq);
    }

    // trailing noop keeps 6 launches per call (same profile alignment as before)
    noop_kernel<<<1, 32>>>();
}

// round 14
// speedup vs baseline: 1.4729x; 1.0258x over previous
#include <cuda_runtime.h>
#include <cuda_fp16.h>
#include <math.h>

#define Bq 64
#define Tq 512
#define Iq 512
#define Hq 1024
#define Oq 512
#define Gq 3072

// -------- scratch (device globals) --------
__device__ float  g_xp[(size_t)Tq * Bq * Gq];      // [t][b][3H] fp32
__device__ __half g_hs16[(size_t)Bq * Tq * Hq];    // [b][t][H]
__device__ uint2  g_hr[2][64 * 64 * 4];            // h ring, fragment layout [k16][b][q]
__device__ __half g_x16[(size_t)Tq * Bq * Iq];     // inputs, [t*64+b][I] fp16
__device__ __half g_wih16[(size_t)Gq * Iq];
__device__ __half g_wout16[(size_t)Oq * Hq];
__device__ unsigned g_flag2[128];                  // arrival counters: +8 per step per block
__device__ unsigned g_gen2 = 0;

// -------- helpers --------
__device__ __forceinline__ unsigned pk2(float a, float b) {
    __half2 h = __floats2half2_rn(a, b);
    return *reinterpret_cast<unsigned*>(&h);
}
__device__ __forceinline__ void mma_f16(
    float& d0, float& d1, float& d2, float& d3,
    unsigned a0, unsigned a1, unsigned a2, unsigned a3,
    unsigned b0, unsigned b1)
{
    asm volatile(
        "mma.sync.aligned.m16n8k16.row.col.f32.f16.f16.f32 "
        "{%0,%1,%2,%3},{%4,%5,%6,%7},{%8,%9},{%0,%1,%2,%3};"
        : "+f"(d0), "+f"(d1), "+f"(d2), "+f"(d3)
        : "r"(a0), "r"(a1), "r"(a2), "r"(a3), "r"(b0), "r"(b1));
}
__device__ __forceinline__ void red_add_release_gpu(unsigned* p, unsigned v) {
    asm volatile("red.add.release.gpu.global.u32 [%0], %1;" :: "l"(p), "r"(v) : "memory");
}
__device__ __forceinline__ unsigned ld_acquire_gpu(const unsigned* p) {
    unsigned v;
    asm volatile("ld.acquire.gpu.global.u32 %0, [%1];" : "=r"(v) : "l"(p) : "memory");
    return v;
}
__device__ __forceinline__ uint2 ldcg_u2(const uint2* p) {
    uint2 v;
    asm volatile("ld.global.cg.v2.u32 {%0,%1}, [%2];" : "=r"(v.x), "=r"(v.y) : "l"(p));
    return v;
}

// MUFU-free sigmoid (FFMA/ALU only)
__device__ __forceinline__ float sigm_fast(float x) {
    const float L2E = 1.4426950408889634f;
    const float MAGIC = 12582912.0f;
    float xc = fminf(fmaxf(x, -87.0f), 87.0f);
    float t = fmaf(xc, -L2E, MAGIC);
    float nf = t - MAGIC;
    float f = fmaf(xc, -L2E, -nf);
    float p = 1.3333558146e-3f;
    p = fmaf(p, f, 9.6181291076e-3f);
    p = fmaf(p, f, 5.5504108665e-2f);
    p = fmaf(p, f, 2.4022650696e-1f);
    p = fmaf(p, f, 6.9314718056e-1f);
    p = fmaf(p, f, 1.0f);
    int ni = __float_as_int(t) - 0x4B400000;
    float sc = __int_as_float((ni << 23) + 0x3F800000);
    float E = p * sc;
    float d = 1.0f + E;
    float r = __int_as_float(0x7EF311C7 - __float_as_int(d));
    r = r * fmaf(-d, r, 2.0f);
    r = r * fmaf(-d, r, 2.0f);
    r = r * fmaf(-d, r, 2.0f);
    return r;
}
__device__ __forceinline__ float tanh_fast(float x) {
    return fmaf(2.0f, sigm_fast(2.0f * x), -1.0f);
}

__global__ void noop_kernel() {}

// ============================================================================
// Merged conversion kernel: x16 [0,8192) | weights [8192,9216) | h0-ring [9216,9232)
// ============================================================================
__global__ __launch_bounds__(256) void cvt_all_kernel(
    const float* __restrict__ inputs, const float* __restrict__ w_ih,
    const float* __restrict__ w_out, const float* __restrict__ h0,
    __half* __restrict__ x16, __half* __restrict__ wih16,
    __half* __restrict__ wout16, uint2* __restrict__ ring1)
{
    const int bid = blockIdx.x;
    const int tid = threadIdx.x;
    if (bid < 8192) {
        const int idx = bid * 256 + tid;
        const int m = idx >> 6;
        const int c = idx & 63;
        const float* src = inputs + ((size_t)(m & 63) * Tq + (size_t)(m >> 6)) * Iq + c * 8;
        const float4 f0 = __ldg((const float4*)src);
        const float4 f1 = __ldg((const float4*)(src + 4));
        uint4 o;
        o.x = pk2(f0.x, f0.y); o.y = pk2(f0.z, f0.w);
        o.z = pk2(f1.x, f1.y); o.w = pk2(f1.z, f1.w);
        *(uint4*)(x16 + (size_t)m * Iq + c * 8) = o;
    } else if (bid < 9216) {
        const int idx = (bid - 8192) * 256 + tid;
        const int NIH = (Gq * Iq) / 8;
        const float* src;
        __half* dst;
        int off;
        if (idx < NIH) { src = w_ih; dst = wih16; off = idx * 8; }
        else           { src = w_out; dst = wout16; off = (idx - NIH) * 8; }
        const float4 f0 = __ldg((const float4*)(src + off));
        const float4 f1 = __ldg((const float4*)(src + off + 4));
        uint4 o;
        o.x = pk2(f0.x, f0.y); o.y = pk2(f0.z, f0.w);
        o.z = pk2(f1.x, f1.y); o.w = pk2(f1.z, f1.w);
        *(uint4*)(dst + off) = o;
    } else {
        const int idx = (bid - 9216) * 256 + tid;   // [0,4096)
        const int b = idx & 63;
        const int k16 = idx >> 6;
        const float* p = h0 + (size_t)b * Hq + k16 * 16;
        const float4 f0 = __ldg((const float4*)p);
        const float4 f1 = __ldg((const float4*)(p + 4));
        const float4 f2 = __ldg((const float4*)(p + 8));
        const float4 f3 = __ldg((const float4*)(p + 12));
        uint2* d = ring1 + ((size_t)k16 * 64 + b) * 4;
        d[0] = make_uint2(pk2(f0.x, f0.y), pk2(f2.x, f2.y));
        d[1] = make_uint2(pk2(f0.z, f0.w), pk2(f2.z, f2.w));
        d[2] = make_uint2(pk2(f1.x, f1.y), pk2(f3.x, f3.y));
        d[3] = make_uint2(pk2(f1.z, f1.w), pk2(f3.z, f3.w));
    }
}

// ============================================================================
// Pure-fp16 MMA GEMM (K1/K3), block tile 128x128, k-tile 64, 256 threads.
// Warp grid 4(m) x 2(n): warp tile 32 x 64 (2 m-tiles x 8 n-tiles).
// Both operands staged in pitch-513 conflict-free pair layout (32.8KB smem).
// ============================================================================
#define APIT 513

__global__ __launch_bounds__(256) void mma_gemm16(
    const __half* __restrict__ A16, const __half* __restrict__ B16,
    const float* __restrict__ bias, float* __restrict__ C,
    int N, int K)
{
    __shared__ __align__(16) uint2 As2[4 * APIT];
    __shared__ __align__(16) uint2 Bs2[4 * APIT];

    const int tid = threadIdx.x;
    const int m0 = blockIdx.y * 128, n0 = blockIdx.x * 128;
    const int lane = tid & 31, warp = tid >> 5;
    const int g = lane >> 2, q = lane & 3;
    const int wm = warp >> 1, wn = warp & 1;

    const int ap = tid & 3;      // k16 plane
    const int ar = tid >> 2;     // row 0..63 (and +64)
    size_t arow[2], brow[2];
#pragma unroll
    for (int i = 0; i < 2; i++) {
        arow[i] = (size_t)(m0 + ar + i * 64) * (size_t)K;
        brow[i] = (size_t)(n0 + ar + i * 64) * (size_t)K;
    }

    float acc[2][8][4];
#pragma unroll
    for (int mt = 0; mt < 2; mt++)
#pragma unroll
        for (int nt = 0; nt < 8; nt++)
#pragma unroll
            for (int e = 0; e < 4; e++) acc[mt][nt][e] = 0.0f;

    uint4 ha[2][2], hb[2][2];
#pragma unroll
    for (int i = 0; i < 2; i++) {
        ha[i][0] = __ldg((const uint4*)(A16 + arow[i] + ap * 16));
        ha[i][1] = __ldg((const uint4*)(A16 + arow[i] + ap * 16 + 8));
        hb[i][0] = __ldg((const uint4*)(B16 + brow[i] + ap * 16));
        hb[i][1] = __ldg((const uint4*)(B16 + brow[i] + ap * 16 + 8));
    }

    for (int k0 = 0; k0 < K; k0 += 64) {
#pragma unroll
        for (int i = 0; i < 2; i++) {
            uint2* da = &As2[ap * APIT + (ar + i * 64) * 4];
            da[0] = make_uint2(ha[i][0].x, ha[i][1].x);
            da[1] = make_uint2(ha[i][0].y, ha[i][1].y);
            da[2] = make_uint2(ha[i][0].z, ha[i][1].z);
            da[3] = make_uint2(ha[i][0].w, ha[i][1].w);
            uint2* db = &Bs2[ap * APIT + (ar + i * 64) * 4];
            db[0] = make_uint2(hb[i][0].x, hb[i][1].x);
            db[1] = make_uint2(hb[i][0].y, hb[i][1].y);
            db[2] = make_uint2(hb[i][0].z, hb[i][1].z);
            db[3] = make_uint2(hb[i][0].w, hb[i][1].w);
        }
        __syncthreads();

        if (k0 + 64 < K) {
#pragma unroll
            for (int i = 0; i < 2; i++) {
                ha[i][0] = __ldg((const uint4*)(A16 + arow[i] + k0 + 64 + ap * 16));
                ha[i][1] = __ldg((const uint4*)(A16 + arow[i] + k0 + 64 + ap * 16 + 8));
                hb[i][0] = __ldg((const uint4*)(B16 + brow[i] + k0 + 64 + ap * 16));
                hb[i][1] = __ldg((const uint4*)(B16 + brow[i] + k0 + 64 + ap * 16 + 8));
            }
        }

#pragma unroll
        for (int p = 0; p < 4; p++) {
            uint2 aLo[2], aHi[2];
#pragma unroll
            for (int mt = 0; mt < 2; mt++) {
                const int r = wm * 32 + mt * 16 + g;
                aLo[mt] = As2[p * APIT + r * 4 + q];
                aHi[mt] = As2[p * APIT + (r + 8) * 4 + q];
            }
#pragma unroll
            for (int nt = 0; nt < 8; nt++) {
                const uint2 bb = Bs2[p * APIT + (wn * 64 + nt * 8 + g) * 4 + q];
#pragma unroll
                for (int mt = 0; mt < 2; mt++)
                    mma_f16(acc[mt][nt][0], acc[mt][nt][1], acc[mt][nt][2], acc[mt][nt][3],
                            aLo[mt].x, aHi[mt].x, aLo[mt].y, aHi[mt].y, bb.x, bb.y);
            }
        }
        __syncthreads();
    }

#pragma unroll
    for (int mt = 0; mt < 2; mt++) {
        const int mrow = m0 + wm * 32 + mt * 16 + g;
#pragma unroll
        for (int nt = 0; nt < 8; nt++) {
            const int col = n0 + wn * 64 + nt * 8 + 2 * q;
            const float2 bb = *(const float2*)&bias[col];
            float2 o0, o1;
            o0.x = acc[mt][nt][0] + bb.x; o0.y = acc[mt][nt][1] + bb.y;
            o1.x = acc[mt][nt][2] + bb.x; o1.y = acc[mt][nt][3] + bb.y;
            *(float2*)&C[(size_t)mrow * N + col] = o0;
            *(float2*)&C[(size_t)(mrow + 8) * N + col] = o1;
        }
    }
}

// ============================================================================
// Persistent GRU recurrence: 128 blocks = 64 col-groups x 2 batch-halves.
// (unchanged from R13 — the validated 2.13ms configuration)
// ============================================================================
#define NB2 128
#define WPLANE 192
#define WS_U2 (64 * WPLANE)
#define REDP 52
#define RED_HALF (8 * 16 * REDP)                      // floats per t-parity buffer
#define K2_SMEM (WS_U2 * 8 + 2 * RED_HALF * 4)        // 98304 + 53248 = 151552 B

__global__ __launch_bounds__(256, 1) void gru_rec_mma(
    const float* __restrict__ xp, const float* __restrict__ h0,
    const float* __restrict__ w_hh, const float* __restrict__ b_hh,
    __half* __restrict__ hs16, float* __restrict__ out_tail)
{
    extern __shared__ uint2 sm2[];
    uint2* Ws2 = sm2;                       // resident weights
    float* Redf0 = (float*)(sm2 + WS_U2);   // k-reduce exchange (x2, by t&1)

    const int tid = threadIdx.x;
    const int lane = tid & 31, warp = tid >> 5;
    const int g = lane >> 2, q = lane & 3;
    const int wk = warp >> 1, wm2 = warp & 1;
    const int cg = blockIdx.x >> 1;         // col group == ring plane this block writes
    const int bh = blockIdx.x & 1;          // batch half
    const int hc0 = cg * 16;
    const int bb0 = bh * 32;

    // resident weights (fp16 pairs), keyed by col group
    for (int idx = tid; idx < WS_U2; idx += 256) {
        const int k16 = idx / WPLANE;
        const int r = idx - k16 * WPLANE;
        const int n = r >> 2, qq = r & 3;
        const float* src = w_hh + ((size_t)(n >> 4) * Hq + hc0 + (n & 15)) * Hq + k16 * 16;
        Ws2[idx] = make_uint2(pk2(src[2 * qq], src[2 * qq + 1]),
                              pk2(src[2 * qq + 8], src[2 * qq + 9]));
    }

    // gate ownership: thread -> row pr = tid>>3 (batch bb0+pr), col pair gcp = tid&7
    const int pr = tid >> 3;
    const int gb = bb0 + pr;
    const int gcp = tid & 7;
    const int hc = hc0 + gcp * 2;
    const float2 bhr = *(const float2*)&b_hh[hc];
    const float2 bhz = *(const float2*)&b_hh[Hq + hc];
    const float2 bhn = *(const float2*)&b_hh[2 * Hq + hc];
    float2 h_prev = *(const float2*)&h0[(size_t)gb * Hq + hc];

    // ring u32 index for this thread's col pair
    const int ru32 = (gcp & 3) * 2 + (gcp >> 2);

    const unsigned G0 = g_gen2;
    __syncthreads();

    for (int t = 0; t < Tq; t++) {
        const uint2* rbuf = g_hr[(t - 1) & 1];
        uint2* rnew = g_hr[t & 1];
        float* Redf = Redf0 + (t & 1) * RED_HALF;

        // xp prefetch (issued before poll; consumed at gates)
        const float* xpb = xp + ((size_t)t * 64 + gb) * Gq + hc;
        const float2 pxr = __ldg((const float2*)xpb);
        const float2 pxz = __ldg((const float2*)(xpb + Hq));
        const float2 pxn = __ldg((const float2*)(xpb + 2 * Hq));

        // ---- warp-local acquire poll: 32 source blocks of this warp's planes ----
        if (t > 0) {
            const unsigned need = 8u * (G0 + (unsigned)t);
            while (ld_acquire_gpu(&g_flag2[wk * 32 + lane]) < need) { }
            __syncwarp();
        }

        // ---- GEMM: warp = m16 x n48 x k256, A direct from L2 ring ----
        float acc[6][4];
#pragma unroll
        for (int nt = 0; nt < 6; nt++)
#pragma unroll
            for (int e = 0; e < 4; e++) acc[nt][e] = 0.0f;

        const int kb = wk * 16;
        const int r0 = bb0 + wm2 * 16 + g;
#pragma unroll
        for (int kk = 0; kk < 16; kk++) {
            const uint2* ra = rbuf + (size_t)(kb + kk) * 256;
            const uint2 aLo = ldcg_u2(ra + r0 * 4 + q);
            const uint2 aHi = ldcg_u2(ra + (r0 + 8) * 4 + q);
            const uint2* wp = Ws2 + (size_t)(kb + kk) * WPLANE;
#pragma unroll
            for (int nt = 0; nt < 6; nt++) {
                const uint2 bb = wp[(nt * 8 + g) * 4 + q];
                mma_f16(acc[nt][0], acc[nt][1], acc[nt][2], acc[nt][3],
                        aLo.x, aHi.x, aLo.y, aHi.y, bb.x, bb.y);
            }
        }

        // ---- publish partials (region = wk*2 + wm2, 16 rows x 48 cols) ----
        {
            float* red = Redf + (wk * 2 + wm2) * (16 * REDP);
#pragma unroll
            for (int nt = 0; nt < 6; nt++) {
                *(float2*)&red[g * REDP + nt * 8 + 2 * q] =
                    make_float2(acc[nt][0], acc[nt][1]);
                *(float2*)&red[(g + 8) * REDP + nt * 8 + 2 * q] =
                    make_float2(acc[nt][2], acc[nt][3]);
            }
        }
        __syncthreads();   // the ONLY block sync per step

        // ---- per-thread reduce + gates (2 outputs) ----
        {
            const int wmb = pr >> 4;
            const int row = pr & 15;
            float sr0 = 0, sr1 = 0, sz0 = 0, sz1 = 0, sn0 = 0, sn1 = 0;
#pragma unroll
            for (int k4 = 0; k4 < 4; k4++) {
                const float* red = Redf + (k4 * 2 + wmb) * (16 * REDP) + row * REDP;
                const float2 vr = *(const float2*)&red[0 * 16 + gcp * 2];
                const float2 vz = *(const float2*)&red[1 * 16 + gcp * 2];
                const float2 vn = *(const float2*)&red[2 * 16 + gcp * 2];
                sr0 += vr.x; sr1 += vr.y;
                sz0 += vz.x; sz1 += vz.y;
                sn0 += vn.x; sn1 += vn.y;
            }
            float hv0, hv1;
            {
                const float r = sigm_fast(pxr.x + sr0 + bhr.x);
                const float z = sigm_fast(pxz.x + sz0 + bhz.x);
                const float nn = tanh_fast(pxn.x + r * (sn0 + bhn.x));
                hv0 = (1.0f - z) * nn + z * h_prev.x;
            }
            {
                const float r = sigm_fast(pxr.y + sr1 + bhr.y);
                const float z = sigm_fast(pxz.y + sz1 + bhz.y);
                const float nn = tanh_fast(pxn.y + r * (sn1 + bhn.y));
                hv1 = (1.0f - z) * nn + z * h_prev.y;
            }
            h_prev = make_float2(hv0, hv1);
            const unsigned p0 = pk2(hv0, hv1);

            // ring write (critical path), then release, then history (off path)
            unsigned* rb32 = (unsigned*)(rnew + ((size_t)cg * 64 + gb) * 4);
            rb32[ru32] = p0;
            __syncwarp();
            if (lane == 0) red_add_release_gpu(&g_flag2[blockIdx.x], 1u);

            *(unsigned*)(hs16 + ((size_t)gb * Tq + t) * Hq + hc) = p0;
            if (t == Tq - 1)
                *(float2*)&out_tail[(size_t)gb * Hq + hc] = make_float2(hv0, hv1);
        }
    }

    if (blockIdx.x == 0 && tid == 0) {
        __threadfence();
        g_gen2 = G0 + (unsigned)Tq;
    }
}

// ============================================================================
extern "C" void kernel_launch(void* const* d_in, const int* in_sizes, int n_in,
                              void* d_out, int out_size)
{
    const float* inputs = (const float*)d_in[0];
    const float* h0     = (const float*)d_in[1];
    const float* w_ih   = (const float*)d_in[2];
    const float* w_hh   = (const float*)d_in[3];
    const float* b_ih   = (const float*)d_in[4];
    const float* b_hh   = (const float*)d_in[5];
    const float* w_out  = (const float*)d_in[6];
    const float* b_out  = (const float*)d_in[7];
    float* out = (float*)d_out;

    float* xp;
    __half *hs16, *x16, *wih16, *wout16;
    uint2* hr;
    cudaGetSymbolAddress((void**)&xp, g_xp);
    cudaGetSymbolAddress((void**)&hs16, g_hs16);
    cudaGetSymbolAddress((void**)&x16, g_x16);
    cudaGetSymbolAddress((void**)&wih16, g_wih16);
    cudaGetSymbolAddress((void**)&wout16, g_wout16);
    cudaGetSymbolAddress((void**)&hr, g_hr);

    // keep gru_rec_mma at overall launch #4 (where the profiler lands)
    noop_kernel<<<1, 32>>>();

    // all conversions in one kernel (x16 | weights | h0 -> ring buf 1)
    cvt_all_kernel<<<9232, 256>>>(inputs, w_ih, w_out, h0,
                                  x16, wih16, wout16, hr + 64 * 64 * 4);

    // K1: x_proj  (128x128 tiles)
    {
        dim3 grid(Gq / 128, (Tq * Bq) / 128);
        mma_gemm16<<<grid, 256>>>(x16, wih16, b_ih, xp, Gq, Iq);
    }

    // K2: persistent GRU recurrence (writes hs16 and the h_last tail directly)
    cudaFuncSetAttribute(gru_rec_mma, cudaFuncAttributeMaxDynamicSharedMemorySize, K2_SMEM);
    gru_rec_mma<<<NB2, 256, K2_SMEM>>>(xp, h0, w_hh, b_hh, hs16,
                                       out + (size_t)Bq * Tq * Oq);

    // K3: out = hs16 @ wout16^T + b_out  (128x128 tiles)
    {
        dim3 grid(Oq / 128, (Bq * Tq) / 128);
        mma_gemm16<<<grid, 256>>>(hs16, wout16, b_out, out, Oq, Hq);
    }

    // trailing noop keeps 6 launches per call (same profile alignment as before)
    noop_kernel<<<1, 32>>>();
}